// round 14
// baseline (speedup 1.0000x reference)
#include <cuda_runtime.h>
#include <math.h>

// ---------------------------------------------------------------------------
// YOLOv4 loss, single launch.
//   blocks [0,356):   conf ch-4 gather, 4 cells/thread front-batched,
//                     PLAIN global loads (sector path, not __ldg/RO path),
//                     BCE-neg via softplus identity (2 MUFU/cell)
//   blocks [356,404): positives, one block per (batch,scale)
//   last block:       finalize + write + reset device state for next replay
// ---------------------------------------------------------------------------

#define NB 16
#define NT 50
#define NA 3
#define NC 80
#define CH 85
#define IMGF 608.0f

#define CELLS0 (NB * NA * 76 * 76)   // 277248
#define CELLS1 (NB * NA * 38 * 38)   // 69312
#define CELLS2 (NB * NA * 19 * 19)   // 17328
#define TPB 256
#define NWARP (TPB / 32)
#define VPT 4
#define CPBLK (TPB * VPT)                  // 1024 cells per conf block
#define CB0 ((CELLS0 + CPBLK - 1) / CPBLK) // 271
#define CB1 ((CELLS1 + CPBLK - 1) / CPBLK) // 68
#define CB2 ((CELLS2 + CPBLK - 1) / CPBLK) // 17
#define NCONF (CB0 + CB1 + CB2)            // 356
#define NPOSBLK (NB * NA)                  // 48
#define NBLK (NCONF + NPOSBLK)             // 404

#define BCE_CAP 23.025850929940457f        // -log(1e-10): reference's clip ceiling

__device__ float    g_acc[3][5];   // {npos, coord, confpos, confneg_corr, cls}
__device__ float    g_negsum[3];
__device__ unsigned g_cnt;

__constant__ float c_anch[3][3][2] = {
    {{12.f,16.f},{19.f,36.f},{40.f,28.f}},
    {{36.f,75.f},{76.f,55.f},{72.f,146.f}},
    {{142.f,110.f},{192.f,243.f},{459.f,401.f}}
};
__constant__ int c_hw[3] = {76, 38, 19};

__device__ __forceinline__ float clip01(float x) { return fminf(fmaxf(x, 0.f), 1.f); }
__device__ __forceinline__ float fsig(float x) {
    return __fdividef(1.f, 1.f + __expf(-x));
}
__device__ __forceinline__ float clip_p(float p) {
    return fminf(fmaxf(p, 1e-10f), 1.0f - 1e-10f);
}

__device__ __forceinline__ float iou_f(float cx1, float cy1, float w1, float h1,
                                       float cx2, float cy2, float w2, float h2) {
    float b1x1 = cx1 - w1 * 0.5f, b1y1 = cy1 - h1 * 0.5f;
    float b1x2 = cx1 + w1 * 0.5f, b1y2 = cy1 + h1 * 0.5f;
    float b2x1 = cx2 - w2 * 0.5f, b2y1 = cy2 - h2 * 0.5f;
    float b2x2 = cx2 + w2 * 0.5f, b2y2 = cy2 + h2 * 0.5f;
    float iw = fmaxf(fminf(b1x2, b2x2) - fmaxf(b1x1, b2x1), 0.f);
    float ih = fmaxf(fminf(b1y2, b2y2) - fmaxf(b1y1, b2y1), 0.f);
    float inter = iw * ih;
    float uni = (b1x2 - b1x1) * (b1y2 - b1y1) + (b2x2 - b2x1) * (b2y2 - b2y1) - inter + 1e-7f;
    return __fdividef(inter, uni);
}

__global__ __launch_bounds__(TPB) void k_fused(
    const float* __restrict__ p0, const float* __restrict__ p1,
    const float* __restrict__ p2, const float* __restrict__ tgt,
    float* __restrict__ out)
{
    const int tid  = threadIdx.x;
    const int lane = tid & 31;
    const int warp = tid >> 5;
    const int blk  = blockIdx.x;

    if (blk < NCONF) {
        // -------- conf gather: 4 cells/thread, PLAIN loads (sector path) ----
        int s, blkInS, N;
        const float* pred;   // deliberately NOT __restrict__-nc: plain LDG.E
        if (blk < CB0)            { s = 0; blkInS = blk;             N = CELLS0; pred = p0; }
        else if (blk < CB0 + CB1) { s = 1; blkInS = blk - CB0;       N = CELLS1; pred = p1; }
        else                      { s = 2; blkInS = blk - CB0 - CB1; N = CELLS2; pred = p2; }

        const int base = blkInS * CPBLK + tid;
        float xv[VPT];
        #pragma unroll
        for (int k = 0; k < VPT; k++) {
            int idx = base + k * TPB;
            float t = -1e30f;
            if (idx < N) {
                // plain global load — avoid the RO/nc path
                asm volatile("ld.global.f32 %0, [%1];"
                             : "=f"(t) : "l"(pred + (size_t)idx * CH + 4));
            }
            xv[k] = t;
        }
        // -log1p(-clip(sigmoid(x))) == min(log(1+e^x), 23.0259); softplus(-1e30)=0
        float v = 0.f;
        #pragma unroll
        for (int k = 0; k < VPT; k++)
            v += fminf(__logf(1.f + __expf(xv[k])), BCE_CAP);

        #pragma unroll
        for (int o = 16; o > 0; o >>= 1) v += __shfl_down_sync(0xffffffffu, v, o);
        __shared__ float red[NWARP];
        if (lane == 0) red[warp] = v;
        __syncthreads();
        if (warp == 0) {
            v = (lane < NWARP) ? red[lane] : 0.f;
            #pragma unroll
            for (int o = 4; o > 0; o >>= 1) v += __shfl_down_sync(0xffffffffu, v, o);
            if (lane == 0) atomicAdd(&g_negsum[s], v);
        }
    } else {
        // ------------- positives: one block per (b, s) -------------
        const int pb = blk - NCONF;
        const int b = pb & 15;
        const int s = pb >> 4;
        const int HW = c_hw[s];
        const float* __restrict__ pred = (s == 0) ? p0 : ((s == 1) ? p1 : p2);

        __shared__ int   sbest[NT], sgx[NT], sgy[NT], sval[NT];
        __shared__ float sbox[NT][4];
        __shared__ float sacc[5];

        if (tid < NT) {
            const float* tr = tgt + (size_t)(b * NT + tid) * CH;
            float x = clip01(tr[0]), y = clip01(tr[1]);
            float w = clip01(tr[2]), h = clip01(tr[3]);
            sbox[tid][0] = x; sbox[tid][1] = y; sbox[tid][2] = w; sbox[tid][3] = h;
            sval[tid] = (tr[4] > 0.f) ? 1 : 0;
            float biou = -1.f; int best = 0;
            #pragma unroll
            for (int a = 0; a < NA; a++) {
                float aw = c_anch[s][a][0] / IMGF;
                float ah = c_anch[s][a][1] / IMGF;
                float io = iou_f(0.5f, 0.5f, aw, ah, x, y, w, h);
                if (io > biou) { biou = io; best = a; }
            }
            sbest[tid] = best;
            int gx = (int)(x * (float)HW);
            int gy = (int)(y * (float)HW);
            sgx[tid] = min(max(gx, 0), HW - 1);
            sgy[tid] = min(max(gy, 0), HW - 1);
        }
        if (tid < 5) sacc[tid] = 0.f;
        __syncthreads();

        for (int t = warp; t < NT; t += NWARP) {
            const int valid = sval[t];
            int conflict = 0;
            if (valid) {
                for (int j = t + 1 + lane; j < NT; j += 32) {
                    if (sval[j] && sbest[j] == sbest[t] && sgx[j] == sgx[t] && sgy[j] == sgy[t])
                        conflict = 1;
                }
            }
            unsigned any = __ballot_sync(0xffffffffu, conflict);
            if (!valid || any) continue;

            const int a = sbest[t], gx = sgx[t], gy = sgy[t];
            const float* cell = pred + ((((size_t)b * NA + a) * HW + gy) * HW + gx) * CH;
            const float* trow = tgt + (size_t)(b * NT + t) * CH;

            float csum = 0.f;
            #pragma unroll
            for (int k = 0; k < 3; k++) {
                int c = lane + 32 * k;
                if (c < NC) {
                    float pc = clip_p(fsig(__ldg(cell + 5 + c)));
                    float tc = clip01(__ldg(trow + 5 + c));
                    csum -= tc * __logf(pc) + (1.f - tc) * __logf(1.f - pc);
                }
            }
            #pragma unroll
            for (int o = 16; o > 0; o >>= 1) csum += __shfl_down_sync(0xffffffffu, csum, o);

            if (lane == 0) {
                float Wf = (float)HW;
                float px = clip01(__fdividef(fsig(cell[0]) + (float)gx, Wf));
                float py = clip01(__fdividef(fsig(cell[1]) + (float)gy, Wf));
                float tw = fminf(fmaxf(cell[2], -10.f), 10.f);
                float th = fminf(fmaxf(cell[3], -10.f), 10.f);
                float pw = clip01(__expf(tw) * (c_anch[s][a][0] / IMGF));
                float ph = clip01(__expf(th) * (c_anch[s][a][1] / IMGF));
                float io = iou_f(px, py, pw, ph, sbox[t][0], sbox[t][1], sbox[t][2], sbox[t][3]);
                float p  = clip_p(fsig(cell[4]));
                atomicAdd(&sacc[0], 1.f);
                atomicAdd(&sacc[1], 1.f - io);
                atomicAdd(&sacc[2], -__logf(p));
                atomicAdd(&sacc[3], -__logf(1.f - p));
                atomicAdd(&sacc[4], csum);
            }
        }
        __syncthreads();
        if (tid < 5 && sacc[tid] != 0.f) atomicAdd(&g_acc[s][tid], sacc[tid]);
    }

    // ------------------ last block: finalize + reset ------------------
    __shared__ int isLast;
    __syncthreads();
    if (tid == 0) {
        __threadfence();
        unsigned c = atomicAdd(&g_cnt, 1u);
        isLast = (c == (unsigned)(NBLK - 1));
    }
    __syncthreads();
    if (isLast && tid == 0) {
        float coord = 0.f, conf = 0.f, cls = 0.f;
        #pragma unroll
        for (int s = 0; s < 3; s++) {
            float HW = (float)c_hw[s];
            float ncells = (float)NB * NA * HW * HW;
            float npos = g_acc[s][0];
            float nneg = ncells - npos;
            float dn = fmaxf(npos, 1.f);
            if (npos > 0.f) coord += g_acc[s][1] / dn;
            conf += g_acc[s][2] / dn + 0.5f * (g_negsum[s] - g_acc[s][3]) / fmaxf(nneg, 1.f);
            if (npos > 0.f) cls += g_acc[s][4] / fmaxf(npos * (float)NC, 1.f);
        }
        out[0] = 5.f * coord + conf + cls;
        out[1] = coord;
        out[2] = conf;
        out[3] = cls;
        #pragma unroll
        for (int i = 0; i < 15; i++) ((float*)g_acc)[i] = 0.f;
        g_negsum[0] = g_negsum[1] = g_negsum[2] = 0.f;
        __threadfence();
        g_cnt = 0u;
    }
}

extern "C" void kernel_launch(void* const* d_in, const int* in_sizes, int n_in,
                              void* d_out, int out_size) {
    const float *p0 = nullptr, *p1 = nullptr, *p2 = nullptr, *tg = nullptr;
    for (int i = 0; i < n_in; i++) {
        switch (in_sizes[i]) {
            case NB * NA * 76 * 76 * CH: p0 = (const float*)d_in[i]; break;
            case NB * NA * 38 * 38 * CH: p1 = (const float*)d_in[i]; break;
            case NB * NA * 19 * 19 * CH: p2 = (const float*)d_in[i]; break;
            case NB * NT * CH:           tg = (const float*)d_in[i]; break;
            default: break;
        }
    }
    k_fused<<<NBLK, TPB>>>(p0, p1, p2, tg, (float*)d_out);
    (void)out_size;
}

// round 15
// speedup vs baseline: 1.6275x; 1.6275x over previous
#include <cuda_runtime.h>
#include <math.h>

// ---------------------------------------------------------------------------
// YOLOv4 loss, single launch.
//   blocks [0,96):  positives, TWO blocks per (batch,scale), softplus BCE
//   rest:           conf ch-4 gather (R10 config: TPB=512, VPT=4, __ldg),
//                   BCE-neg via softplus identity
//   last block:     finalize + write + reset device state for next replay
// ---------------------------------------------------------------------------

#define NB 16
#define NT 50
#define NA 3
#define NC 80
#define CH 85
#define IMGF 608.0f

#define CELLS0 (NB * NA * 76 * 76)   // 277248
#define CELLS1 (NB * NA * 38 * 38)   // 69312
#define CELLS2 (NB * NA * 19 * 19)   // 17328
#define TPB 512
#define NWARP (TPB / 32)                   // 16
#define VPT 4
#define CPBLK (TPB * VPT)                  // 2048
#define CB0 ((CELLS0 + CPBLK - 1) / CPBLK) // 136
#define CB1 ((CELLS1 + CPBLK - 1) / CPBLK) // 34
#define CB2 ((CELLS2 + CPBLK - 1) / CPBLK) // 9
#define PSPLIT 2
#define NPOSBLK (NB * NA * PSPLIT)         // 96
#define NBLK (NPOSBLK + CB0 + CB1 + CB2)   // 275

#define BCE_CAP 23.025850929940457f        // -log(1e-10): reference clip ceiling

__device__ float    g_acc[3][5];   // {npos, coord, confpos, confneg_corr, cls}
__device__ float    g_negsum[3];
__device__ unsigned g_cnt;

__constant__ float c_anch[3][3][2] = {
    {{12.f,16.f},{19.f,36.f},{40.f,28.f}},
    {{36.f,75.f},{76.f,55.f},{72.f,146.f}},
    {{142.f,110.f},{192.f,243.f},{459.f,401.f}}
};
__constant__ int c_hw[3] = {76, 38, 19};

__device__ __forceinline__ float clip01(float x) { return fminf(fmaxf(x, 0.f), 1.f); }
__device__ __forceinline__ float fsig(float x) {
    return __fdividef(1.f, 1.f + __expf(-x));
}
// softplus(x) = log(1+e^x); exact BCE pieces with the reference's 1e-10 clips:
//   -log(sigmoid(x))   = min(softplus(x) - x, CAP)   [== softplus(-x) capped]
//   -log(1-sigmoid(x)) = min(softplus(x),     CAP)
__device__ __forceinline__ float fsoftplus(float x) {
    return __logf(1.f + __expf(x));
}

__device__ __forceinline__ float iou_f(float cx1, float cy1, float w1, float h1,
                                       float cx2, float cy2, float w2, float h2) {
    float b1x1 = cx1 - w1 * 0.5f, b1y1 = cy1 - h1 * 0.5f;
    float b1x2 = cx1 + w1 * 0.5f, b1y2 = cy1 + h1 * 0.5f;
    float b2x1 = cx2 - w2 * 0.5f, b2y1 = cy2 - h2 * 0.5f;
    float b2x2 = cx2 + w2 * 0.5f, b2y2 = cy2 + h2 * 0.5f;
    float iw = fmaxf(fminf(b1x2, b2x2) - fmaxf(b1x1, b2x1), 0.f);
    float ih = fmaxf(fminf(b1y2, b2y2) - fmaxf(b1y1, b2y1), 0.f);
    float inter = iw * ih;
    float uni = (b1x2 - b1x1) * (b1y2 - b1y1) + (b2x2 - b2x1) * (b2y2 - b2y1) - inter + 1e-7f;
    return __fdividef(inter, uni);
}

__global__ __launch_bounds__(TPB) void k_fused(
    const float* __restrict__ p0, const float* __restrict__ p1,
    const float* __restrict__ p2, const float* __restrict__ tgt,
    float* __restrict__ out)
{
    const int tid  = threadIdx.x;
    const int lane = tid & 31;
    const int warp = tid >> 5;
    const int blk  = blockIdx.x;

    if (blk < NPOSBLK) {
        // ---- positives: PSPLIT blocks per (b,s); each decodes all targets,
        //      processes an interleaved subset ----
        const int bs   = blk >> 1;          // 0..47
        const int part = blk & 1;           // 0..PSPLIT-1
        const int b = bs & 15;
        const int s = bs >> 4;
        const int HW = c_hw[s];
        const float* __restrict__ pred = (s == 0) ? p0 : ((s == 1) ? p1 : p2);

        __shared__ int   sbest[NT], sgx[NT], sgy[NT], sval[NT];
        __shared__ float sbox[NT][4];
        __shared__ float sacc[5];

        if (tid < NT) {
            const float* tr = tgt + (size_t)(b * NT + tid) * CH;
            float x = clip01(tr[0]), y = clip01(tr[1]);
            float w = clip01(tr[2]), h = clip01(tr[3]);
            sbox[tid][0] = x; sbox[tid][1] = y; sbox[tid][2] = w; sbox[tid][3] = h;
            sval[tid] = (tr[4] > 0.f) ? 1 : 0;
            float biou = -1.f; int best = 0;
            #pragma unroll
            for (int a = 0; a < NA; a++) {
                float aw = c_anch[s][a][0] / IMGF;
                float ah = c_anch[s][a][1] / IMGF;
                float io = iou_f(0.5f, 0.5f, aw, ah, x, y, w, h);
                if (io > biou) { biou = io; best = a; }
            }
            sbest[tid] = best;
            int gx = (int)(x * (float)HW);
            int gy = (int)(y * (float)HW);
            sgx[tid] = min(max(gx, 0), HW - 1);
            sgy[tid] = min(max(gy, 0), HW - 1);
        }
        if (tid < 5) sacc[tid] = 0.f;
        __syncthreads();

        // global warp index across the PSPLIT sibling blocks
        for (int t = part * NWARP + warp; t < NT; t += NWARP * PSPLIT) {
            const int valid = sval[t];
            int conflict = 0;
            if (valid) {
                for (int j = t + 1 + lane; j < NT; j += 32) {
                    if (sval[j] && sbest[j] == sbest[t] && sgx[j] == sgx[t] && sgy[j] == sgy[t])
                        conflict = 1;
                }
            }
            unsigned any = __ballot_sync(0xffffffffu, conflict);
            if (!valid || any) continue;

            const int a = sbest[t], gx = sgx[t], gy = sgy[t];
            const float* cell = pred + ((((size_t)b * NA + a) * HW + gy) * HW + gx) * CH;
            const float* trow = tgt + (size_t)(b * NT + t) * CH;

            // class BCE via softplus: 2 MUFU per class
            float csum = 0.f;
            #pragma unroll
            for (int k = 0; k < 3; k++) {
                int c = lane + 32 * k;
                if (c < NC) {
                    float x  = __ldg(cell + 5 + c);
                    float tc = clip01(__ldg(trow + 5 + c));
                    float sp = fsoftplus(x);
                    csum += (1.f - tc) * fminf(sp, BCE_CAP)
                          + tc * fminf(sp - x, BCE_CAP);
                }
            }
            #pragma unroll
            for (int o = 16; o > 0; o >>= 1) csum += __shfl_down_sync(0xffffffffu, csum, o);

            if (lane == 0) {
                float Wf = (float)HW;
                float px = clip01(__fdividef(fsig(cell[0]) + (float)gx, Wf));
                float py = clip01(__fdividef(fsig(cell[1]) + (float)gy, Wf));
                float tw = fminf(fmaxf(cell[2], -10.f), 10.f);
                float th = fminf(fmaxf(cell[3], -10.f), 10.f);
                float pw = clip01(__expf(tw) * (c_anch[s][a][0] / IMGF));
                float ph = clip01(__expf(th) * (c_anch[s][a][1] / IMGF));
                float io = iou_f(px, py, pw, ph, sbox[t][0], sbox[t][1], sbox[t][2], sbox[t][3]);
                float xc = cell[4];
                float sp = fsoftplus(xc);
                atomicAdd(&sacc[0], 1.f);
                atomicAdd(&sacc[1], 1.f - io);
                atomicAdd(&sacc[2], fminf(sp - xc, BCE_CAP));  // -log(p)
                atomicAdd(&sacc[3], fminf(sp, BCE_CAP));       // -log(1-p) correction
                atomicAdd(&sacc[4], csum);
            }
        }
        __syncthreads();
        if (tid < 5 && sacc[tid] != 0.f) atomicAdd(&g_acc[s][tid], sacc[tid]);

    } else {
        // -------- conf gather: R10 config (4 cells/thread, __ldg) --------
        int cid = blk - NPOSBLK;
        int s, blkInS, N;
        const float* __restrict__ pred;
        if (cid < CB0)            { s = 0; blkInS = cid;             N = CELLS0; pred = p0; }
        else if (cid < CB0 + CB1) { s = 1; blkInS = cid - CB0;       N = CELLS1; pred = p1; }
        else                      { s = 2; blkInS = cid - CB0 - CB1; N = CELLS2; pred = p2; }

        const int base = blkInS * CPBLK + tid;
        float xv[VPT];
        #pragma unroll
        for (int k = 0; k < VPT; k++) {
            int idx = base + k * TPB;
            xv[k] = (idx < N) ? __ldg(pred + (size_t)idx * CH + 4) : -1e30f;
        }
        float v = 0.f;
        #pragma unroll
        for (int k = 0; k < VPT; k++)
            v += fminf(fsoftplus(xv[k]), BCE_CAP);   // softplus(-1e30)=0

        #pragma unroll
        for (int o = 16; o > 0; o >>= 1) v += __shfl_down_sync(0xffffffffu, v, o);
        __shared__ float red[NWARP];
        if (lane == 0) red[warp] = v;
        __syncthreads();
        if (warp == 0) {
            v = (lane < NWARP) ? red[lane] : 0.f;
            #pragma unroll
            for (int o = 8; o > 0; o >>= 1) v += __shfl_down_sync(0xffffffffu, v, o);
            if (lane == 0) atomicAdd(&g_negsum[s], v);
        }
    }

    // ------------------ last block: finalize + reset ------------------
    __shared__ int isLast;
    __syncthreads();
    if (tid == 0) {
        __threadfence();
        unsigned c = atomicAdd(&g_cnt, 1u);
        isLast = (c == (unsigned)(NBLK - 1));
    }
    __syncthreads();
    if (isLast && tid == 0) {
        float coord = 0.f, conf = 0.f, cls = 0.f;
        #pragma unroll
        for (int s = 0; s < 3; s++) {
            float HW = (float)c_hw[s];
            float ncells = (float)NB * NA * HW * HW;
            float npos = g_acc[s][0];
            float nneg = ncells - npos;
            float dn = fmaxf(npos, 1.f);
            if (npos > 0.f) coord += g_acc[s][1] / dn;
            conf += g_acc[s][2] / dn + 0.5f * (g_negsum[s] - g_acc[s][3]) / fmaxf(nneg, 1.f);
            if (npos > 0.f) cls += g_acc[s][4] / fmaxf(npos * (float)NC, 1.f);
        }
        out[0] = 5.f * coord + conf + cls;
        out[1] = coord;
        out[2] = conf;
        out[3] = cls;
        #pragma unroll
        for (int i = 0; i < 15; i++) ((float*)g_acc)[i] = 0.f;
        g_negsum[0] = g_negsum[1] = g_negsum[2] = 0.f;
        __threadfence();
        g_cnt = 0u;
    }
}

extern "C" void kernel_launch(void* const* d_in, const int* in_sizes, int n_in,
                              void* d_out, int out_size) {
    const float *p0 = nullptr, *p1 = nullptr, *p2 = nullptr, *tg = nullptr;
    for (int i = 0; i < n_in; i++) {
        switch (in_sizes[i]) {
            case NB * NA * 76 * 76 * CH: p0 = (const float*)d_in[i]; break;
            case NB * NA * 38 * 38 * CH: p1 = (const float*)d_in[i]; break;
            case NB * NA * 19 * 19 * CH: p2 = (const float*)d_in[i]; break;
            case NB * NT * CH:           tg = (const float*)d_in[i]; break;
            default: break;
        }
    }
    k_fused<<<NBLK, TPB>>>(p0, p1, p2, tg, (float*)d_out);
    (void)out_size;
}